// round 1
// baseline (speedup 1.0000x reference)
#include <cuda_runtime.h>
#include <math.h>

// Problem constants
#define NTOK 2048          // B*S = 2*1024 tokens
#define DDIM 1024          // model dim
#define NEXP 14            // experts
#define FDIM 2048          // ffn dim

// ---------------- device scratch (allocation-free rule: __device__ globals) ---
__device__ int   g_count[NEXP];
__device__ int   g_offset[NEXP];
__device__ int   g_pairs[NEXP][NTOK];      // value = token*2 + slot
__device__ float g_gatew[NTOK][2];         // normalized top-2 weights
__device__ float g_h1[2 * NTOK][FDIM];     // gemm1 output, indexed by offset[e]+m
__device__ float g_out2[2 * NTOK][DDIM];   // gemm2 output, indexed by pair id

// ---------------- kernel: zero expert counts --------------------------------
__global__ void zero_kernel() {
    if (threadIdx.x < NEXP) g_count[threadIdx.x] = 0;
}

// ---------------- kernel: gating (logits -> softmax top2 -> routing lists) --
__global__ void gate_kernel(const float* __restrict__ x,
                            const float* __restrict__ gw) {
    int n = blockIdx.x;
    __shared__ float sx[DDIM];
    __shared__ float red[128];
    __shared__ float logits[NEXP];
    const float* xr = x + (size_t)n * DDIM;
    for (int d = threadIdx.x; d < DDIM; d += 128) sx[d] = xr[d];
    __syncthreads();
    for (int e = 0; e < NEXP; e++) {
        const float* w = gw + (size_t)e * DDIM;
        float s = 0.f;
        for (int d = threadIdx.x; d < DDIM; d += 128) s += sx[d] * w[d];
        red[threadIdx.x] = s;
        __syncthreads();
        #pragma unroll
        for (int st = 64; st > 0; st >>= 1) {
            if (threadIdx.x < st) red[threadIdx.x] += red[threadIdx.x + st];
            __syncthreads();
        }
        if (threadIdx.x == 0) logits[e] = red[0];
        __syncthreads();
    }
    if (threadIdx.x == 0) {
        // top-2 with earliest-index tie-break (matches jax.lax.top_k)
        int i0 = 0; float l0 = logits[0];
        for (int e = 1; e < NEXP; e++) if (logits[e] > l0) { l0 = logits[e]; i0 = e; }
        int i1 = -1; float l1 = -3.0e38f;
        for (int e = 0; e < NEXP; e++) if (e != i0 && logits[e] > l1) { l1 = logits[e]; i1 = e; }
        // renormalized top-2 softmax weights: softmax denominators cancel
        float p1 = expf(l1 - l0);           // p0 = 1
        float inv = 1.0f / (1.0f + p1);
        g_gatew[n][0] = inv;
        g_gatew[n][1] = p1 * inv;
        int s0 = atomicAdd(&g_count[i0], 1);
        g_pairs[i0][s0] = n * 2 + 0;
        int s1 = atomicAdd(&g_count[i1], 1);
        g_pairs[i1][s1] = n * 2 + 1;
    }
}

// ---------------- kernel: exclusive prefix over counts ----------------------
__global__ void prefix_kernel() {
    if (threadIdx.x == 0) {
        int s = 0;
        for (int e = 0; e < NEXP; e++) { g_offset[e] = s; s += g_count[e]; }
    }
}

// ---------------- GEMM1: h1 = gelu(gather(x) @ w1[e] + b1[e]) ----------------
// Tile 64x64x16, 256 threads, 4x4 per thread.
__global__ void __launch_bounds__(256)
gemm1_kernel(const float* __restrict__ x,
             const float* __restrict__ w1,
             const float* __restrict__ b1) {
    int e   = blockIdx.z;
    int mt  = blockIdx.y;
    int cnt = g_count[e];
    if (mt * 64 >= cnt) return;
    int nt  = blockIdx.x;
    int off = g_offset[e];

    __shared__ float As[16][68];
    __shared__ float Bs[16][68];
    __shared__ int rowtok[64];

    int tid = threadIdx.x;
    int tx = tid & 15, ty = tid >> 4;

    if (tid < 64) {
        int m = mt * 64 + tid;
        rowtok[tid] = (m < cnt) ? (g_pairs[e][m] >> 1) : -1;
    }
    __syncthreads();

    float acc[4][4] = {};
    const float* B0 = w1 + (size_t)e * DDIM * FDIM + nt * 64;

    for (int k0 = 0; k0 < DDIM; k0 += 16) {
        // A tile: 64 rows x 16 k, one float4 per thread (row-contiguous)
        {
            int m = tid >> 2;
            int k = (tid & 3) * 4;
            int t = rowtok[m];
            float4 v = make_float4(0.f, 0.f, 0.f, 0.f);
            if (t >= 0)
                v = *reinterpret_cast<const float4*>(x + (size_t)t * DDIM + k0 + k);
            As[k + 0][m] = v.x; As[k + 1][m] = v.y;
            As[k + 2][m] = v.z; As[k + 3][m] = v.w;
        }
        // B tile: 16 k x 64 n, coalesced rows
        #pragma unroll
        for (int i = 0; i < 4; i++) {
            int idx = tid + 256 * i;
            int nn = idx & 63, k = idx >> 6;
            Bs[k][nn] = B0[(size_t)(k0 + k) * FDIM + nn];
        }
        __syncthreads();
        #pragma unroll
        for (int kk = 0; kk < 16; kk++) {
            float4 a = *reinterpret_cast<const float4*>(&As[kk][ty * 4]);
            float4 b = *reinterpret_cast<const float4*>(&Bs[kk][tx * 4]);
            float av[4] = {a.x, a.y, a.z, a.w};
            float bv[4] = {b.x, b.y, b.z, b.w};
            #pragma unroll
            for (int i = 0; i < 4; i++)
                #pragma unroll
                for (int j = 0; j < 4; j++)
                    acc[i][j] += av[i] * bv[j];
        }
        __syncthreads();
    }

    #pragma unroll
    for (int i = 0; i < 4; i++) {
        int m = mt * 64 + ty * 4 + i;
        if (m >= cnt) continue;
        float* hrow = g_h1[off + m];
        #pragma unroll
        for (int j = 0; j < 4; j++) {
            int f = nt * 64 + tx * 4 + j;
            float v = acc[i][j] + b1[(size_t)e * FDIM + f];
            v = 0.5f * v * (1.0f + erff(v * 0.70710678118654752440f));  // exact gelu
            hrow[f] = v;
        }
    }
}

// ---------------- GEMM2: out2 = h1 @ w2[e] + b2[e] ---------------------------
__global__ void __launch_bounds__(256)
gemm2_kernel(const float* __restrict__ w2,
             const float* __restrict__ b2) {
    int e   = blockIdx.z;
    int mt  = blockIdx.y;
    int cnt = g_count[e];
    if (mt * 64 >= cnt) return;
    int nt  = blockIdx.x;
    int off = g_offset[e];

    __shared__ float As[16][68];
    __shared__ float Bs[16][68];
    __shared__ int pairid[64];

    int tid = threadIdx.x;
    int tx = tid & 15, ty = tid >> 4;

    if (tid < 64) {
        int m = mt * 64 + tid;
        pairid[tid] = (m < cnt) ? g_pairs[e][m] : -1;
    }
    __syncthreads();

    float acc[4][4] = {};
    const float* B0 = w2 + (size_t)e * FDIM * DDIM + nt * 64;

    for (int k0 = 0; k0 < FDIM; k0 += 16) {
        {
            int m = tid >> 2;
            int k = (tid & 3) * 4;
            int mm = mt * 64 + m;
            float4 v = make_float4(0.f, 0.f, 0.f, 0.f);
            if (mm < cnt)
                v = *reinterpret_cast<const float4*>(&g_h1[off + mm][k0 + k]);
            As[k + 0][m] = v.x; As[k + 1][m] = v.y;
            As[k + 2][m] = v.z; As[k + 3][m] = v.w;
        }
        #pragma unroll
        for (int i = 0; i < 4; i++) {
            int idx = tid + 256 * i;
            int nn = idx & 63, k = idx >> 6;
            Bs[k][nn] = B0[(size_t)(k0 + k) * DDIM + nn];
        }
        __syncthreads();
        #pragma unroll
        for (int kk = 0; kk < 16; kk++) {
            float4 a = *reinterpret_cast<const float4*>(&As[kk][ty * 4]);
            float4 b = *reinterpret_cast<const float4*>(&Bs[kk][tx * 4]);
            float av[4] = {a.x, a.y, a.z, a.w};
            float bv[4] = {b.x, b.y, b.z, b.w};
            #pragma unroll
            for (int i = 0; i < 4; i++)
                #pragma unroll
                for (int j = 0; j < 4; j++)
                    acc[i][j] += av[i] * bv[j];
        }
        __syncthreads();
    }

    #pragma unroll
    for (int i = 0; i < 4; i++) {
        int m = mt * 64 + ty * 4 + i;
        if (m >= cnt) continue;
        int p = pairid[ty * 4 + i];
        float* orow = g_out2[p];
        #pragma unroll
        for (int j = 0; j < 4; j++) {
            int d = nt * 64 + tx * 4 + j;
            orow[d] = acc[i][j] + b2[(size_t)e * DDIM + d];
        }
    }
}

// ---------------- combine: out = clip(x + w0*o0 + w1*o1, +-100) --------------
__global__ void combine_kernel(const float* __restrict__ x,
                               float* __restrict__ out) {
    int i = blockIdx.x * 256 + threadIdx.x;
    int n = i >> 10;          // / DDIM
    int d = i & 1023;
    float v = x[i]
            + g_gatew[n][0] * g_out2[2 * n + 0][d]
            + g_gatew[n][1] * g_out2[2 * n + 1][d];
    out[i] = fminf(fmaxf(v, -100.0f), 100.0f);
}

// ---------------- launch -----------------------------------------------------
extern "C" void kernel_launch(void* const* d_in, const int* in_sizes, int n_in,
                              void* d_out, int out_size) {
    const float* h      = (const float*)d_in[0];   // (2,1024,1024)
    const float* gate_w = (const float*)d_in[1];   // (14,1024)
    const float* w1     = (const float*)d_in[2];   // (14,1024,2048)
    const float* b1     = (const float*)d_in[3];   // (14,2048)
    const float* w2     = (const float*)d_in[4];   // (14,2048,1024)
    const float* b2     = (const float*)d_in[5];   // (14,1024)
    float* out = (float*)d_out;

    zero_kernel<<<1, 32>>>();
    gate_kernel<<<NTOK, 128>>>(h, gate_w);
    prefix_kernel<<<1, 32>>>();
    gemm1_kernel<<<dim3(FDIM / 64, NTOK / 64, NEXP), 256>>>(h, w1, b1);
    gemm2_kernel<<<dim3(DDIM / 64, NTOK / 64, NEXP), 256>>>(w2, b2);
    combine_kernel<<<(NTOK * DDIM) / 256, 256>>>(h, out);
}